// round 1
// baseline (speedup 1.0000x reference)
#include <cuda_runtime.h>
#include <cuda_bf16.h>

#define NN 102400
#define EE 1638400
#define ET (EE + NN)   // 1740800 edges incl self loops
#define GG 256
#define HH 4
#define CC 32

// ---------------- scratch (device globals; no allocation) ----------------
__device__ float g_h1[NN * 128];     // layer1 projected features
__device__ float g_als1[NN * 4];     // attn logits src, layer1
__device__ float g_ald1[NN * 4];     // attn logits dst, layer1
__device__ float g_den1[NN * 4];     // softmax denominators, layer1
__device__ float g_out1[NN * 128];   // unnormalized aggregate, layer1
__device__ float g_h2[NN * 32];
__device__ float g_als2[NN];
__device__ float g_ald2[NN];
__device__ float g_den2[NN];
__device__ float g_out2[NN * 32];

// ---------------- init: zero accumulators ----------------
__global__ void init_kernel() {
    long i = blockIdx.x * (long)blockDim.x + threadIdx.x;
    long stride = (long)gridDim.x * blockDim.x;
    float4 z = make_float4(0.f, 0.f, 0.f, 0.f);
    float4* o1 = (float4*)g_out1;
    for (long j = i; j < (long)NN * 32; j += stride) o1[j] = z;
    float4* o2 = (float4*)g_out2;
    for (long j = i; j < (long)NN * 8; j += stride) o2[j] = z;
    float4* d1 = (float4*)g_den1;
    for (long j = i; j < (long)NN; j += stride) d1[j] = z;
    for (long j = i; j < (long)NN; j += stride) g_den2[j] = 0.f;
}

// ---------------- gemm1: h1 = x @ W1 ; attn logits per node ----------------
// block = 128 threads (thread t owns output column t), 16 nodes per block.
__global__ void gemm1_kernel(const float* __restrict__ x,
                             const float* __restrict__ W1,
                             const float* __restrict__ a_src1,
                             const float* __restrict__ a_dst1) {
    __shared__ float xs[16 * 64];
    int col = threadIdx.x;
    float w[64];
#pragma unroll
    for (int k = 0; k < 64; k++) w[k] = W1[k * 128 + col];
    float asw = a_src1[col], adw = a_dst1[col];
    int node0 = blockIdx.x * 16;
    for (int j = threadIdx.x; j < 16 * 64; j += 128) xs[j] = x[node0 * 64 + j];
    __syncthreads();
    int lane = col & 31, wp = col >> 5;   // wp == head
    for (int nl = 0; nl < 16; nl++) {
        float acc = 0.f;
        const float4* xv = (const float4*)&xs[nl * 64];
#pragma unroll
        for (int k4 = 0; k4 < 16; k4++) {
            float4 xx = xv[k4];
            acc += xx.x * w[4 * k4 + 0];
            acc += xx.y * w[4 * k4 + 1];
            acc += xx.z * w[4 * k4 + 2];
            acc += xx.w * w[4 * k4 + 3];
        }
        int n = node0 + nl;
        g_h1[n * 128 + col] = acc;
        float ps = acc * asw, pd = acc * adw;
#pragma unroll
        for (int off = 16; off; off >>= 1) {
            ps += __shfl_xor_sync(0xffffffffu, ps, off);
            pd += __shfl_xor_sync(0xffffffffu, pd, off);
        }
        if (lane == 0) {
            g_als1[n * 4 + wp] = ps;
            g_ald1[n * 4 + wp] = pd;
        }
    }
}

// ---------------- edge pass layer 1: warp per edge ----------------
// out1[dst] += exp(lrelu(als[src]+ald[dst])) * h1[src] ; den1[dst] += exp(...)
__global__ void edge1_kernel(const int* __restrict__ ei) {
    long t = blockIdx.x * (long)blockDim.x + threadIdx.x;
    long gw = t >> 5;
    if (gw >= ET) return;
    int lane = (int)(t & 31);
    int s, d;
    if (gw < EE) {
        s = ei[gw];
        d = ei[EE + gw];
    } else {
        s = d = (int)(gw - EE);
    }
    int h = lane >> 3;
    float e = g_als1[4 * s + h] + g_ald1[4 * d + h];
    e = (e > 0.f) ? e : 0.2f * e;
    float wgt = __expf(e);
    if ((lane & 7) == 0) atomicAdd(&g_den1[4 * d + h], wgt);
    float4 v = *(const float4*)&g_h1[128 * s + 4 * lane];
    v.x *= wgt; v.y *= wgt; v.z *= wgt; v.w *= wgt;
    float* dp = &g_out1[128 * d + 4 * lane];
    asm volatile("red.global.add.v4.f32 [%0], {%1,%2,%3,%4};" ::
                 "l"(dp), "f"(v.x), "f"(v.y), "f"(v.z), "f"(v.w) : "memory");
}

// ---------------- gemm2: normalize+b1+ELU, then @ W2, attn logits ----------------
// block = 128 threads, 64 nodes per block (16 tiles of 4 nodes).
__global__ void gemm2_kernel(const float* __restrict__ W2,
                             const float* __restrict__ b1,
                             const float* __restrict__ a2s,
                             const float* __restrict__ a2d) {
    __shared__ float sWt[32 * 132];   // transposed W2, padded rows
    __shared__ float sb[128];
    __shared__ float sg[4 * 128];
    for (int j = threadIdx.x; j < 4096; j += 128) {
        int k = j >> 5, c = j & 31;
        sWt[c * 132 + k] = W2[j];
    }
    if (threadIdx.x < 128) sb[threadIdx.x] = b1[threadIdx.x];
    int lane = threadIdx.x & 31, wp = threadIdx.x >> 5;
    float a_s = a2s[lane], a_d = a2d[lane];
    for (int tile = 0; tile < 16; tile++) {
        int node0 = blockIdx.x * 64 + tile * 4;
        __syncthreads();
        for (int j = threadIdx.x; j < 512; j += 128) {
            int nl = j >> 7, k = j & 127;
            int n = node0 + nl;
            float v = g_out1[n * 128 + k] / g_den1[4 * n + (k >> 5)] + sb[k];
            sg[nl * 128 + k] = (v > 0.f) ? v : (__expf(v) - 1.f);
        }
        __syncthreads();
        float acc = 0.f;
        const float4* wv = (const float4*)&sWt[lane * 132];
        const float4* gv = (const float4*)&sg[wp * 128];
#pragma unroll
        for (int k4 = 0; k4 < 32; k4++) {
            float4 ww = wv[k4];
            float4 gg = gv[k4];
            acc += gg.x * ww.x + gg.y * ww.y + gg.z * ww.z + gg.w * ww.w;
        }
        int n = node0 + wp;
        g_h2[n * 32 + lane] = acc;
        float ps = acc * a_s, pd = acc * a_d;
#pragma unroll
        for (int off = 16; off; off >>= 1) {
            ps += __shfl_xor_sync(0xffffffffu, ps, off);
            pd += __shfl_xor_sync(0xffffffffu, pd, off);
        }
        if (lane == 0) { g_als2[n] = ps; g_ald2[n] = pd; }
    }
}

// ---------------- edge pass layer 2: 8 lanes per edge (4 edges/warp) ----------------
__global__ void edge2_kernel(const int* __restrict__ ei) {
    long t = blockIdx.x * (long)blockDim.x + threadIdx.x;
    long gw = t >> 5;
    int lane = (int)(t & 31);
    long e4 = gw * 4 + (lane >> 3);
    if (e4 >= ET) return;
    int sub = lane & 7;
    int s, d;
    if (e4 < EE) {
        s = ei[e4];
        d = ei[EE + e4];
    } else {
        s = d = (int)(e4 - EE);
    }
    float e = g_als2[s] + g_ald2[d];
    e = (e > 0.f) ? e : 0.2f * e;
    float wgt = __expf(e);
    if (sub == 0) atomicAdd(&g_den2[d], wgt);
    float4 v = *(const float4*)&g_h2[32 * s + 4 * sub];
    v.x *= wgt; v.y *= wgt; v.z *= wgt; v.w *= wgt;
    float* dp = &g_out2[32 * d + 4 * sub];
    asm volatile("red.global.add.v4.f32 [%0], {%1,%2,%3,%4};" ::
                 "l"(dp), "f"(v.x), "f"(v.y), "f"(v.z), "f"(v.w) : "memory");
}

// ---------------- pool (mean over 400 nodes/graph) + classifier MLP ----------------
__global__ void pool_kernel(const float* __restrict__ clinical,
                            const float* __restrict__ b2,
                            const float* __restrict__ Wc1,
                            const float* __restrict__ bc1,
                            const float* __restrict__ Wc2,
                            const float* __restrict__ bc2,
                            float* __restrict__ out) {
    int g = blockIdx.x;           // 256 graphs
    __shared__ float red[128];
    __shared__ float sf[37];
    __shared__ float sz[16];
    int t = threadIdx.x;          // 128 threads
    int c = t & 31, r0 = t >> 5;
    float bb = b2[c];
    float sum = 0.f;
    for (int r = r0; r < 400; r += 4) {
        int n = g * 400 + r;
        float v = g_out2[n * 32 + c] / g_den2[n] + bb;
        sum += (v > 0.f) ? v : (__expf(v) - 1.f);
    }
    red[t] = sum;
    __syncthreads();
    if (t < 32) {
        float s2 = red[t] + red[t + 32] + red[t + 64] + red[t + 96];
        sf[t] = s2 * (1.f / 400.f);
    }
    if (t >= 32 && t < 37) sf[t] = clinical[g * 5 + (t - 32)];
    __syncthreads();
    if (t < 16) {
        float z = bc1[t];
#pragma unroll
        for (int i = 0; i < 37; i++) z += sf[i] * Wc1[i * 16 + t];
        sz[t] = (z > 0.f) ? z : (__expf(z) - 1.f);
    }
    __syncthreads();
    if (t == 0) {
        float o = bc2[0];
#pragma unroll
        for (int j = 0; j < 16; j++) o += sz[j] * Wc2[j];
        out[g] = o;
    }
}

// ---------------- launch ----------------
extern "C" void kernel_launch(void* const* d_in, const int* in_sizes, int n_in,
                              void* d_out, int out_size) {
    const float* x       = (const float*)d_in[0];
    const int*   ei      = (const int*)d_in[1];
    // d_in[2] = batch (layout known: 400 nodes/graph, sorted) — unused
    const float* clinical= (const float*)d_in[3];
    const float* W1      = (const float*)d_in[4];
    const float* a_src1  = (const float*)d_in[5];
    const float* a_dst1  = (const float*)d_in[6];
    const float* b1      = (const float*)d_in[7];
    const float* W2      = (const float*)d_in[8];
    const float* a_src2  = (const float*)d_in[9];
    const float* a_dst2  = (const float*)d_in[10];
    const float* b2      = (const float*)d_in[11];
    const float* Wc1     = (const float*)d_in[12];
    const float* bc1     = (const float*)d_in[13];
    const float* Wc2     = (const float*)d_in[14];
    const float* bc2     = (const float*)d_in[15];
    float* out = (float*)d_out;

    init_kernel<<<2048, 256>>>();
    gemm1_kernel<<<NN / 16, 128>>>(x, W1, a_src1, a_dst1);
    {
        long threads = (long)ET * 32;
        int blocks = (int)((threads + 255) / 256);
        edge1_kernel<<<blocks, 256>>>(ei);
    }
    gemm2_kernel<<<NN / 64, 128>>>(W2, b1, a_src2, a_dst2);
    {
        long warps = ET / 4;              // ET divisible by 4
        long threads = warps * 32;
        int blocks = (int)((threads + 255) / 256);
        edge2_kernel<<<blocks, 256>>>(ei);
    }
    pool_kernel<<<GG, 128>>>(clinical, b2, Wc1, bc1, Wc2, bc2, out);
}

// round 3
// speedup vs baseline: 1.5182x; 1.5182x over previous
#include <cuda_runtime.h>
#include <cuda_fp16.h>

#define NN 102400
#define EE 1638400
#define ET (EE + NN)   // edges incl self loops
#define GG 256
#define FULL 0xffffffffu

// ---------------- scratch (device globals; no allocation) ----------------
__device__ __align__(16) __half g_h1h[NN * 128];   // layer1 projected features (fp16)
__device__ __align__(16) float  g_als1[NN * 4];
__device__ __align__(16) float  g_ald1[NN * 4];
__device__ __align__(16) __half g_h2h[NN * 32];    // layer2 projected features (fp16)
__device__ __align__(16) float  g_als2[NN];
__device__ __align__(16) float  g_ald2[NN];
__device__ __align__(16) int    g_cnt[NN];
__device__ __align__(16) int    g_rowptr[NN + 4];
__device__ __align__(16) int    g_pos[NN];
__device__ __align__(16) int    g_csr[ET];
__device__ __align__(16) float  g_pool[GG * 32];

__device__ __forceinline__ float eluf(float v) {
    return (v > 0.f) ? v : (__expf(v) - 1.f);
}
__device__ __forceinline__ float lrelu(float e) {
    return (e > 0.f) ? e : 0.2f * e;
}

// ---------------- CSR build ----------------
__global__ void k_init() {
    int i = blockIdx.x * blockDim.x + threadIdx.x;
    if (i < NN) g_cnt[i] = 1;          // self loop pre-counted
    if (i < GG * 32) g_pool[i] = 0.f;
}

__global__ void k_hist(const int* __restrict__ ei) {
    int e = blockIdx.x * blockDim.x + threadIdx.x;
    if (e < EE) atomicAdd(&g_cnt[ei[EE + e]], 1);
}

// single block, 1024 threads, 100 elements each (1024*100 == NN)
__global__ void k_scan() {
    __shared__ int sp[1024];
    int t = threadIdx.x;
    const int4* cv = (const int4*)(g_cnt + t * 100);
    int s = 0;
#pragma unroll
    for (int i = 0; i < 25; i++) {
        int4 c = cv[i];
        s += c.x + c.y + c.z + c.w;
    }
    sp[t] = s;
    __syncthreads();
    for (int off = 1; off < 1024; off <<= 1) {
        int v = (t >= off) ? sp[t - off] : 0;
        __syncthreads();
        sp[t] += v;
        __syncthreads();
    }
    int run = t ? sp[t - 1] : 0;
    int4* rp = (int4*)(g_rowptr + t * 100);
    int4* pp = (int4*)(g_pos + t * 100);
#pragma unroll
    for (int i = 0; i < 25; i++) {
        int4 c = cv[i];
        int4 r;
        r.x = run; run += c.x;
        r.y = run; run += c.y;
        r.z = run; run += c.z;
        r.w = run; run += c.w;
        rp[i] = r;
        pp[i] = r;
    }
    if (t == 1023) g_rowptr[NN] = ET;
}

__global__ void k_scatter(const int* __restrict__ ei) {
    int e = blockIdx.x * blockDim.x + threadIdx.x;
    if (e >= ET) return;
    int s, d;
    if (e < EE) { s = ei[e]; d = ei[EE + e]; }
    else        { s = d = e - EE; }
    int p = atomicAdd(&g_pos[d], 1);
    g_csr[p] = s;
}

// ---------------- gemm1: h1 = x @ W1 (fp16 out) + attn logits ----------------
__global__ void k_gemm1(const float* __restrict__ x,
                        const float* __restrict__ W1,
                        const float* __restrict__ a_src1,
                        const float* __restrict__ a_dst1) {
    __shared__ float xs[16 * 64];
    int col = threadIdx.x;                 // output column 0..127
    float w[64];
#pragma unroll
    for (int k = 0; k < 64; k++) w[k] = W1[k * 128 + col];
    float asw = a_src1[col], adw = a_dst1[col];
    int node0 = blockIdx.x * 16;
    for (int j = threadIdx.x; j < 16 * 64; j += 128) xs[j] = x[node0 * 64 + j];
    __syncthreads();
    int lane = col & 31, wp = col >> 5;    // wp == head
    for (int nl = 0; nl < 16; nl++) {
        float acc = 0.f;
        const float4* xv = (const float4*)&xs[nl * 64];
#pragma unroll
        for (int k4 = 0; k4 < 16; k4++) {
            float4 xx = xv[k4];
            acc += xx.x * w[4 * k4 + 0];
            acc += xx.y * w[4 * k4 + 1];
            acc += xx.z * w[4 * k4 + 2];
            acc += xx.w * w[4 * k4 + 3];
        }
        int n = node0 + nl;
        float other = __shfl_xor_sync(FULL, acc, 1);
        if (!(col & 1))
            ((__half2*)g_h1h)[(n * 128 + col) >> 1] = __floats2half2_rn(acc, other);
        float ps = acc * asw, pd = acc * adw;
#pragma unroll
        for (int off = 16; off; off >>= 1) {
            ps += __shfl_xor_sync(FULL, ps, off);
            pd += __shfl_xor_sync(FULL, pd, off);
        }
        if (lane == 0) {
            g_als1[n * 4 + wp] = ps;
            g_ald1[n * 4 + wp] = pd;
        }
    }
}

// ---------------- fused: gather layer1 + softmax-normalize + ELU + GEMM2 + logits2 ----------------
// warp per 4 dst nodes; 8 warps/block.
__global__ void __launch_bounds__(256) k_edge1(const float* __restrict__ W2,
                                               const float* __restrict__ b1,
                                               const float* __restrict__ a2s,
                                               const float* __restrict__ a2d) {
    __shared__ float sWt[32 * 132];   // sWt[c*132 + k] = W2[k][c], padded
    __shared__ float sb[128];
    int tid = threadIdx.x;
    for (int j = tid; j < 4096; j += 256) {
        int k = j >> 5, c = j & 31;
        sWt[c * 132 + k] = W2[j];
    }
    if (tid < 128) sb[tid] = b1[tid];
    __syncthreads();

    int lane = tid & 31;
    int warp = (blockIdx.x << 3) + (tid >> 5);
    int d0 = warp * 4;
    int head = lane >> 3;

    float4 a[4];
#pragma unroll
    for (int n = 0; n < 4; n++) {
        int d = d0 + n;
        float ald = g_ald1[4 * d + head];
        int beg = g_rowptr[d], end = g_rowptr[d + 1];
        float4 acc = make_float4(0.f, 0.f, 0.f, 0.f);
        float den = 0.f;
        for (int j = beg; j < end; j++) {
            int s = g_csr[j];
            float e = lrelu(g_als1[4 * s + head] + ald);
            float wv = __expf(e);
            den += wv;
            // row = 128 halves = 32 float2; lane reads halves [4*lane, 4*lane+4)
            float2 raw = ((const float2*)g_h1h)[(s << 5) + lane];
            __half2 p0 = *(__half2*)&raw.x;
            __half2 p1 = *(__half2*)&raw.y;
            float2 f0 = __half22float2(p0);
            float2 f1 = __half22float2(p1);
            acc.x += wv * f0.x;
            acc.y += wv * f0.y;
            acc.z += wv * f1.x;
            acc.w += wv * f1.y;
        }
        float inv = 1.f / den;
        float4 bb = *(const float4*)&sb[lane * 4];
        a[n].x = eluf(acc.x * inv + bb.x);
        a[n].y = eluf(acc.y * inv + bb.y);
        a[n].z = eluf(acc.z * inv + bb.z);
        a[n].w = eluf(acc.w * inv + bb.w);
    }

    // shuffle GEMM: o[n][col=lane] = sum_k a[n][k] * W2[k][lane]
    float o[4] = {0.f, 0.f, 0.f, 0.f};
#pragma unroll
    for (int sl = 0; sl < 32; sl++) {
        float4 w4 = *(const float4*)&sWt[lane * 132 + 4 * sl];
#pragma unroll
        for (int n = 0; n < 4; n++) {
            float ax = __shfl_sync(FULL, a[n].x, sl);
            float ay = __shfl_sync(FULL, a[n].y, sl);
            float az = __shfl_sync(FULL, a[n].z, sl);
            float aw = __shfl_sync(FULL, a[n].w, sl);
            o[n] += ax * w4.x + ay * w4.y + az * w4.z + aw * w4.w;
        }
    }

    float als = a2s[lane], aldv = a2d[lane];
#pragma unroll
    for (int n = 0; n < 4; n++) {
        g_h2h[(d0 + n) * 32 + lane] = __float2half(o[n]);
        float ps = o[n] * als, pd = o[n] * aldv;
#pragma unroll
        for (int off = 16; off; off >>= 1) {
            ps += __shfl_xor_sync(FULL, ps, off);
            pd += __shfl_xor_sync(FULL, pd, off);
        }
        if (lane == 0) {
            g_als2[d0 + n] = ps;
            g_ald2[d0 + n] = pd;
        }
    }
}

// ---------------- layer2 gather + ELU + pooled reduction ----------------
// warp per dst node, 2 edges per iteration (half-warps).
__global__ void __launch_bounds__(256) k_edge2(const float* __restrict__ b2) {
    int lane = threadIdx.x & 31;
    int d = (blockIdx.x << 3) + (threadIdx.x >> 5);
    int hw = lane >> 4;            // which edge of the pair
    int c2 = (lane & 15) << 1;     // column base (2 cols per lane)
    float ald = g_ald2[d];
    int beg = g_rowptr[d], end = g_rowptr[d + 1];
    float ax = 0.f, ay = 0.f, den = 0.f;
    for (int j = beg; j < end; j += 2) {
        int jj = j + hw;
        bool valid = jj < end;
        int s = g_csr[valid ? jj : beg];
        float e = lrelu(g_als2[s] + ald);
        float wv = valid ? __expf(e) : 0.f;
        den += wv;
        __half2 hv = *(const __half2*)(g_h2h + s * 32 + c2);
        float2 f = __half22float2(hv);
        ax += wv * f.x;
        ay += wv * f.y;
    }
    den += __shfl_xor_sync(FULL, den, 16);
    ax  += __shfl_xor_sync(FULL, ax, 16);
    ay  += __shfl_xor_sync(FULL, ay, 16);
    if (hw == 0) {
        float inv = 1.f / den;
        float vx = eluf(ax * inv + b2[c2]);
        float vy = eluf(ay * inv + b2[c2 + 1]);
        int g = d / 400;
        atomicAdd(&g_pool[g * 32 + c2], vx);
        atomicAdd(&g_pool[g * 32 + c2 + 1], vy);
    }
}

// ---------------- classifier MLP ----------------
__global__ void k_mlp(const float* __restrict__ clinical,
                      const float* __restrict__ Wc1,
                      const float* __restrict__ bc1,
                      const float* __restrict__ Wc2,
                      const float* __restrict__ bc2,
                      float* __restrict__ out) {
    int g = blockIdx.x;
    int t = threadIdx.x;   // 64
    __shared__ float sf[37];
    __shared__ float sz[16];
    if (t < 32) sf[t] = g_pool[g * 32 + t] * (1.f / 400.f);
    else if (t < 37) sf[t] = clinical[g * 5 + (t - 32)];
    __syncthreads();
    if (t < 16) {
        float z = bc1[t];
#pragma unroll
        for (int i = 0; i < 37; i++) z += sf[i] * Wc1[i * 16 + t];
        sz[t] = eluf(z);
    }
    __syncthreads();
    if (t == 0) {
        float o = bc2[0];
#pragma unroll
        for (int j = 0; j < 16; j++) o += sz[j] * Wc2[j];
        out[g] = o;
    }
}

// ---------------- launch ----------------
extern "C" void kernel_launch(void* const* d_in, const int* in_sizes, int n_in,
                              void* d_out, int out_size) {
    const float* x        = (const float*)d_in[0];
    const int*   ei       = (const int*)d_in[1];
    const float* clinical = (const float*)d_in[3];
    const float* W1       = (const float*)d_in[4];
    const float* a_src1   = (const float*)d_in[5];
    const float* a_dst1   = (const float*)d_in[6];
    const float* b1       = (const float*)d_in[7];
    const float* W2       = (const float*)d_in[8];
    const float* a_src2   = (const float*)d_in[9];
    const float* a_dst2   = (const float*)d_in[10];
    const float* b2       = (const float*)d_in[11];
    const float* Wc1      = (const float*)d_in[12];
    const float* bc1      = (const float*)d_in[13];
    const float* Wc2      = (const float*)d_in[14];
    const float* bc2      = (const float*)d_in[15];
    float* out = (float*)d_out;

    k_init<<<(NN + 255) / 256, 256>>>();
    k_hist<<<EE / 256, 256>>>(ei);
    k_scan<<<1, 1024>>>();
    k_scatter<<<ET / 256, 256>>>(ei);
    k_gemm1<<<NN / 16, 128>>>(x, W1, a_src1, a_dst1);
    k_edge1<<<NN / 32, 256>>>(W2, b1, a_src2, a_dst2);
    k_edge2<<<NN / 8, 256>>>(b2);
    k_mlp<<<GG, 64>>>(clinical, Wc1, bc1, Wc2, bc2, out);
}

// round 4
// speedup vs baseline: 1.5504x; 1.0212x over previous
#include <cuda_runtime.h>
#include <cuda_fp16.h>

#define NN 102400
#define EE 1638400
#define ET (EE + NN)   // edges incl self loops
#define GG 256
#define FULL 0xffffffffu

// ---------------- scratch (device globals; no allocation) ----------------
__device__ __align__(16) __half g_h1h[NN * 128];   // layer1 projected features (fp16)
__device__ __align__(16) float  g_als1[NN * 4];
__device__ __align__(16) float  g_ald1[NN * 4];
__device__ __align__(16) __half g_h2h[NN * 32];    // layer2 projected features (fp16)
__device__ __align__(16) float  g_als2[NN];
__device__ __align__(16) float  g_ald2[NN];
__device__ __align__(16) int    g_cnt[NN];
__device__ __align__(16) int    g_rowptr[NN + 4];
__device__ __align__(16) int    g_pos[NN];
__device__ __align__(16) int    g_csr[ET];
__device__ __align__(16) float  g_pool[GG * 32];

__device__ __forceinline__ float eluf(float v) {
    return (v > 0.f) ? v : (__expf(v) - 1.f);
}
__device__ __forceinline__ float lrelu(float e) {
    return (e > 0.f) ? e : 0.2f * e;
}

// ---------------- CSR build ----------------
__global__ void k_init() {
    int i = blockIdx.x * blockDim.x + threadIdx.x;
    if (i < NN) g_cnt[i] = 1;          // self loop pre-counted
    if (i < GG * 32) g_pool[i] = 0.f;
}

__global__ void k_hist(const int* __restrict__ ei) {
    int e = blockIdx.x * blockDim.x + threadIdx.x;
    if (e < EE) atomicAdd(&g_cnt[ei[EE + e]], 1);
}

// single block, 1024 threads, 100 elements each (1024*100 == NN)
__global__ void k_scan() {
    __shared__ int sp[1024];
    int t = threadIdx.x;
    const int4* cv = (const int4*)(g_cnt + t * 100);
    int s = 0;
#pragma unroll
    for (int i = 0; i < 25; i++) {
        int4 c = cv[i];
        s += c.x + c.y + c.z + c.w;
    }
    sp[t] = s;
    __syncthreads();
    for (int off = 1; off < 1024; off <<= 1) {
        int v = (t >= off) ? sp[t - off] : 0;
        __syncthreads();
        sp[t] += v;
        __syncthreads();
    }
    int run = t ? sp[t - 1] : 0;
    int4* rp = (int4*)(g_rowptr + t * 100);
    int4* pp = (int4*)(g_pos + t * 100);
#pragma unroll
    for (int i = 0; i < 25; i++) {
        int4 c = cv[i];
        int4 r;
        r.x = run; run += c.x;
        r.y = run; run += c.y;
        r.z = run; run += c.z;
        r.w = run; run += c.w;
        rp[i] = r;
        pp[i] = r;
    }
    if (t == 1023) g_rowptr[NN] = ET;
}

__global__ void k_scatter(const int* __restrict__ ei) {
    int e = blockIdx.x * blockDim.x + threadIdx.x;
    if (e >= ET) return;
    int s, d;
    if (e < EE) { s = ei[e]; d = ei[EE + e]; }
    else        { s = d = e - EE; }
    int p = atomicAdd(&g_pos[d], 1);
    g_csr[p] = s;
}

// ---------------- gemm1: h1 = x @ W1 (fp16 out) + attn logits ----------------
__global__ void k_gemm1(const float* __restrict__ x,
                        const float* __restrict__ W1,
                        const float* __restrict__ a_src1,
                        const float* __restrict__ a_dst1) {
    __shared__ float xs[16 * 64];
    int col = threadIdx.x;                 // output column 0..127
    float w[64];
#pragma unroll
    for (int k = 0; k < 64; k++) w[k] = W1[k * 128 + col];
    float asw = a_src1[col], adw = a_dst1[col];
    int node0 = blockIdx.x * 16;
    for (int j = threadIdx.x; j < 16 * 64; j += 128) xs[j] = x[node0 * 64 + j];
    __syncthreads();
    int lane = col & 31, wp = col >> 5;    // wp == head
    for (int nl = 0; nl < 16; nl++) {
        float acc = 0.f;
        const float4* xv = (const float4*)&xs[nl * 64];
#pragma unroll
        for (int k4 = 0; k4 < 16; k4++) {
            float4 xx = xv[k4];
            acc += xx.x * w[4 * k4 + 0];
            acc += xx.y * w[4 * k4 + 1];
            acc += xx.z * w[4 * k4 + 2];
            acc += xx.w * w[4 * k4 + 3];
        }
        int n = node0 + nl;
        float other = __shfl_xor_sync(FULL, acc, 1);
        if (!(col & 1))
            ((__half2*)g_h1h)[(n * 128 + col) >> 1] = __floats2half2_rn(acc, other);
        float ps = acc * asw, pd = acc * adw;
#pragma unroll
        for (int off = 16; off; off >>= 1) {
            ps += __shfl_xor_sync(FULL, ps, off);
            pd += __shfl_xor_sync(FULL, pd, off);
        }
        if (lane == 0) {
            g_als1[n * 4 + wp] = ps;
            g_ald1[n * 4 + wp] = pd;
        }
    }
}

// ---------------- fused: gather layer1 + softmax-normalize + ELU + GEMM2 + logits2 ----------------
// warp per 4 dst nodes; 8 warps/block. Edge loop unrolled x4 for MLP.
__global__ void __launch_bounds__(256) k_edge1(const float* __restrict__ W2,
                                               const float* __restrict__ b1,
                                               const float* __restrict__ a2s,
                                               const float* __restrict__ a2d) {
    __shared__ float sWt[32 * 132];   // sWt[c*132 + k] = W2[k][c], padded
    __shared__ float sb[128];
    int tid = threadIdx.x;
    for (int j = tid; j < 4096; j += 256) {
        int k = j >> 5, c = j & 31;
        sWt[c * 132 + k] = W2[j];
    }
    if (tid < 128) sb[tid] = b1[tid];
    __syncthreads();

    int lane = tid & 31;
    int warp = (blockIdx.x << 3) + (tid >> 5);
    int d0 = warp * 4;
    int head = lane >> 3;

    const float2* h1v = (const float2*)g_h1h;

    float4 a[4];
#pragma unroll
    for (int n = 0; n < 4; n++) {
        int d = d0 + n;
        float ald = g_ald1[4 * d + head];
        int beg = g_rowptr[d], end = g_rowptr[d + 1];
        float4 acc = make_float4(0.f, 0.f, 0.f, 0.f);
        float den = 0.f;
        int j = beg;
        for (; j + 4 <= end; j += 4) {
            int s0 = g_csr[j];
            int s1 = g_csr[j + 1];
            int s2 = g_csr[j + 2];
            int s3 = g_csr[j + 3];
            float l0 = g_als1[4 * s0 + head];
            float l1 = g_als1[4 * s1 + head];
            float l2 = g_als1[4 * s2 + head];
            float l3 = g_als1[4 * s3 + head];
            float2 r0 = h1v[(s0 << 5) + lane];
            float2 r1 = h1v[(s1 << 5) + lane];
            float2 r2 = h1v[(s2 << 5) + lane];
            float2 r3 = h1v[(s3 << 5) + lane];
            float w0 = __expf(lrelu(l0 + ald));
            float w1 = __expf(lrelu(l1 + ald));
            float w2 = __expf(lrelu(l2 + ald));
            float w3 = __expf(lrelu(l3 + ald));
            den += (w0 + w1) + (w2 + w3);
            float2 f;
#define ACC4(R, W)                                              \
            f = __half22float2(*(__half2*)&(R).x);              \
            acc.x += (W) * f.x; acc.y += (W) * f.y;             \
            f = __half22float2(*(__half2*)&(R).y);              \
            acc.z += (W) * f.x; acc.w += (W) * f.y;
            ACC4(r0, w0) ACC4(r1, w1) ACC4(r2, w2) ACC4(r3, w3)
        }
        for (; j < end; j++) {
            int s = g_csr[j];
            float wv = __expf(lrelu(g_als1[4 * s + head] + ald));
            den += wv;
            float2 raw = h1v[(s << 5) + lane];
            float2 f;
            ACC4(raw, wv)
#undef ACC4
        }
        float inv = 1.f / den;
        float4 bb = *(const float4*)&sb[lane * 4];
        a[n].x = eluf(acc.x * inv + bb.x);
        a[n].y = eluf(acc.y * inv + bb.y);
        a[n].z = eluf(acc.z * inv + bb.z);
        a[n].w = eluf(acc.w * inv + bb.w);
    }

    // shuffle GEMM: o[n][col=lane] = sum_k a[n][k] * W2[k][lane]
    float o[4] = {0.f, 0.f, 0.f, 0.f};
#pragma unroll
    for (int sl = 0; sl < 32; sl++) {
        float4 w4 = *(const float4*)&sWt[lane * 132 + 4 * sl];
#pragma unroll
        for (int n = 0; n < 4; n++) {
            float ax = __shfl_sync(FULL, a[n].x, sl);
            float ay = __shfl_sync(FULL, a[n].y, sl);
            float az = __shfl_sync(FULL, a[n].z, sl);
            float aw = __shfl_sync(FULL, a[n].w, sl);
            o[n] += ax * w4.x + ay * w4.y + az * w4.z + aw * w4.w;
        }
    }

    float als = a2s[lane], aldv = a2d[lane];
#pragma unroll
    for (int n = 0; n < 4; n++) {
        g_h2h[(d0 + n) * 32 + lane] = __float2half(o[n]);
        float ps = o[n] * als, pd = o[n] * aldv;
#pragma unroll
        for (int off = 16; off; off >>= 1) {
            ps += __shfl_xor_sync(FULL, ps, off);
            pd += __shfl_xor_sync(FULL, pd, off);
        }
        if (lane == 0) {
            g_als2[d0 + n] = ps;
            g_ald2[d0 + n] = pd;
        }
    }
}

// ---------------- layer2 gather + ELU + pooled reduction ----------------
// warp per dst node; half-warp per edge, unrolled x2 (4 edges in flight).
__global__ void __launch_bounds__(256) k_edge2(const float* __restrict__ b2) {
    int lane = threadIdx.x & 31;
    int d = (blockIdx.x << 3) + (threadIdx.x >> 5);
    int hw = lane >> 4;            // which edge of the pair
    int c2 = (lane & 15) << 1;     // column base (2 cols per lane)
    float ald = g_ald2[d];
    int beg = g_rowptr[d], end = g_rowptr[d + 1];
    float ax = 0.f, ay = 0.f, den = 0.f;
    int j = beg;
    for (; j + 4 <= end; j += 4) {
        int s0 = g_csr[j + hw];
        int s1 = g_csr[j + 2 + hw];
        float l0 = g_als2[s0];
        float l1 = g_als2[s1];
        __half2 v0 = *(const __half2*)(g_h2h + s0 * 32 + c2);
        __half2 v1 = *(const __half2*)(g_h2h + s1 * 32 + c2);
        float w0 = __expf(lrelu(l0 + ald));
        float w1 = __expf(lrelu(l1 + ald));
        den += w0 + w1;
        float2 f0 = __half22float2(v0);
        float2 f1 = __half22float2(v1);
        ax += w0 * f0.x + w1 * f1.x;
        ay += w0 * f0.y + w1 * f1.y;
    }
    for (; j < end; j += 2) {
        int jj = j + hw;
        bool valid = jj < end;
        int s = g_csr[valid ? jj : beg];
        float e = lrelu(g_als2[s] + ald);
        float wv = valid ? __expf(e) : 0.f;
        den += wv;
        __half2 hv = *(const __half2*)(g_h2h + s * 32 + c2);
        float2 f = __half22float2(hv);
        ax += wv * f.x;
        ay += wv * f.y;
    }
    den += __shfl_xor_sync(FULL, den, 16);
    ax  += __shfl_xor_sync(FULL, ax, 16);
    ay  += __shfl_xor_sync(FULL, ay, 16);
    if (hw == 0) {
        float inv = 1.f / den;
        float vx = eluf(ax * inv + b2[c2]);
        float vy = eluf(ay * inv + b2[c2 + 1]);
        int g = d / 400;
        atomicAdd(&g_pool[g * 32 + c2], vx);
        atomicAdd(&g_pool[g * 32 + c2 + 1], vy);
    }
}

// ---------------- classifier MLP ----------------
__global__ void k_mlp(const float* __restrict__ clinical,
                      const float* __restrict__ Wc1,
                      const float* __restrict__ bc1,
                      const float* __restrict__ Wc2,
                      const float* __restrict__ bc2,
                      float* __restrict__ out) {
    int g = blockIdx.x;
    int t = threadIdx.x;   // 64
    __shared__ float sf[37];
    __shared__ float sz[16];
    if (t < 32) sf[t] = g_pool[g * 32 + t] * (1.f / 400.f);
    else if (t < 37) sf[t] = clinical[g * 5 + (t - 32)];
    __syncthreads();
    if (t < 16) {
        float z = bc1[t];
#pragma unroll
        for (int i = 0; i < 37; i++) z += sf[i] * Wc1[i * 16 + t];
        sz[t] = eluf(z);
    }
    __syncthreads();
    if (t == 0) {
        float o = bc2[0];
#pragma unroll
        for (int j = 0; j < 16; j++) o += sz[j] * Wc2[j];
        out[g] = o;
    }
}

// ---------------- launch ----------------
extern "C" void kernel_launch(void* const* d_in, const int* in_sizes, int n_in,
                              void* d_out, int out_size) {
    const float* x        = (const float*)d_in[0];
    const int*   ei       = (const int*)d_in[1];
    const float* clinical = (const float*)d_in[3];
    const float* W1       = (const float*)d_in[4];
    const float* a_src1   = (const float*)d_in[5];
    const float* a_dst1   = (const float*)d_in[6];
    const float* b1       = (const float*)d_in[7];
    const float* W2       = (const float*)d_in[8];
    const float* a_src2   = (const float*)d_in[9];
    const float* a_dst2   = (const float*)d_in[10];
    const float* b2       = (const float*)d_in[11];
    const float* Wc1      = (const float*)d_in[12];
    const float* bc1      = (const float*)d_in[13];
    const float* Wc2      = (const float*)d_in[14];
    const float* bc2      = (const float*)d_in[15];
    float* out = (float*)d_out;

    k_init<<<(NN + 255) / 256, 256>>>();
    k_hist<<<EE / 256, 256>>>(ei);
    k_scan<<<1, 1024>>>();
    k_scatter<<<ET / 256, 256>>>(ei);
    k_gemm1<<<NN / 16, 128>>>(x, W1, a_src1, a_dst1);
    k_edge1<<<NN / 32, 256>>>(W2, b1, a_src2, a_dst2);
    k_edge2<<<NN / 8, 256>>>(b2);
    k_mlp<<<GG, 64>>>(clinical, Wc1, bc1, Wc2, bc2, out);
}